// round 8
// baseline (speedup 1.0000x reference)
#include <cuda_runtime.h>
#include <math.h>

#define Bn 64
#define Tn 1024
#define Kn 128
#define NT 256
#define TAG_START 126
#define TAG_STOP  127
#define NEGV -10000.0f
#define LOG2E 1.4426950408889634f
#define LN2   0.6931471805599453f

__device__ float g_partial[Bn];
__device__ unsigned int g_count = 0;

#define FMA2(acc, x, y) \
    asm("fma.rn.f32x2 %0, %1, %2, %0;" : "+l"(acc) : "l"(x), "l"(y))

#define ADD2(dst, x, y) \
    asm("add.rn.f32x2 %0, %1, %2;" : "=l"(dst) : "l"(x), "l"(y))

#define PACK2(dst, lo, hi) \
    asm("mov.b64 %0, {%1, %2};" : "=l"(dst) : "f"(lo), "f"(hi))

#define UNPACK2(lo, hi, src) \
    asm("mov.b64 {%0, %1}, %2;" : "=f"(lo), "=f"(hi) : "l"(src))

#define SHFL_BFLY16(dst, src) \
    asm("shfl.sync.bfly.b32 %0, %1, 16, 0x1f, 0xffffffff;" : "=f"(dst) : "f"(src))

__device__ __forceinline__ float ex2(float x) {
    float r; asm("ex2.approx.f32 %0, %1;" : "=f"(r) : "f"(x)); return r;
}
__device__ __forceinline__ float lg2(float x) {
    float r; asm("lg2.approx.f32 %0, %1;" : "=f"(r) : "f"(x)); return r;
}

__global__ __launch_bounds__(NT, 1) void crf_fwd_kernel(
    const float* __restrict__ feats,
    const int*   __restrict__ tags,
    const int*   __restrict__ lens,
    const float* __restrict__ trans,
    float*       __restrict__ out)
{
    const int b   = blockIdx.x;
    const int tid = threadIdx.x;
    const int w   = tid >> 5;
    const int l   = tid & 31;
    const int half = l >> 4;                 // 0: inputs [0,64), 1: [64,128)
    const int jj  = (w << 4) | (l & 15);     // output tag (pair (l, l^16) shares jj)
    const bool renorm_lane = (tid == 240);   // warp 7 (issues first), computes w[112]

    const float* fb = feats + (size_t)b * Tn * Kn;
    const int*   tb = tags + b * Tn;
    const int    len = lens[b];

    __shared__ __align__(16) float eAs[2][Kn];
    __shared__ float sv0[2];                 // lagged power-of-2 scale
    __shared__ float red[NT];
    __shared__ float sh_gold;
    __shared__ int   sh_last;

    // ---------------- gold score ----------------
    float gsum = 0.f;
    for (int t = tid; t < Tn; t += NT) {
        if (t < len)     gsum += fb[t * Kn + tb[t]];
        if (t < len - 1) gsum += trans[tb[t + 1] * Kn + tb[t]];
    }
    red[tid] = gsum;
    __syncthreads();
    #pragma unroll
    for (int s = NT / 2; s > 0; s >>= 1) {
        if (tid < s) red[tid] += red[tid + s];
        __syncthreads();
    }
    if (tid == 0) sh_gold = red[0];

    // ---------------- exp(trans) half-row into 32 regs ----------------
    unsigned long long eT2[32];
    const float* trow = trans + jj * Kn + half * 64;
    #pragma unroll
    for (int i = 0; i < 32; i++) {
        float e0 = ex2(trow[2 * i]     * LOG2E);
        float e1 = ex2(trow[2 * i + 1] * LOG2E);
        PACK2(eT2[i], e0, e1);
    }

    // ---------------- init (linear domain) ----------------
    float f0s = fb[TAG_START];
    float c2f = f0s * LOG2E;
    if (l < 16) eAs[0][jj] = (jj == TAG_START) ? 1.f : 0.f;
    if (tid < 2) sv0[tid] = 1.f;
    int c2i = 0;                             // uniform across all lanes

    // depth-3 feat prefetch: ef = exp(feat[t]); pA, pB in flight
    float f1 = (1 < len) ? fb[1 * Kn + jj] : 0.f;
    float pA = (2 < len) ? fb[2 * Kn + jj] : 0.f;
    float pB = (3 < len) ? fb[3 * Kn + jj] : 0.f;
    float ef = ex2(f1 * LOG2E);

    // ---------------- one forward step ----------------
    auto step = [&](int t, int cur, int nxt,
                    const float* __restrict__ src, float* __restrict__ dst) {
        float pC = (t + 3 < len) ? fb[(t + 3) * Kn + jj] : 0.f;
        float ef_next = ex2(pA * LOG2E);

        __syncthreads();                     // publishes eAs[cur], sv0[cur]
        float sc  = sv0[cur];
        float efs = ef * sc;                 // off the critical chain

        const ulonglong2* __restrict__ pV = (const ulonglong2*)(src + half * 64);
        unsigned long long acc0 = 0ull, acc1 = 0ull;
        #pragma unroll
        for (int i = 0; i < 16; i++) {
            ulonglong2 p = pV[i];            // LDS.128 broadcast
            FMA2(acc0, p.x, eT2[2 * i]);
            FMA2(acc1, p.y, eT2[2 * i + 1]);
        }
        unsigned long long sall;
        ADD2(sall, acc0, acc1);
        float lo, hi;
        UNPACK2(lo, hi, sall);
        float part = lo + hi;

        float other;
        SHFL_BFLY16(other, part);
        float wv = (part + other) * efs;

        if (l < 16) dst[jj] = wv;            // predicated STS
        // next scale 2^-e via exponent-field arithmetic (all lanes, no branch)
        float nsc = __int_as_float((254 << 23) - (__float_as_int(wv) & 0x7f800000));
        if (renorm_lane) sv0[nxt] = nsc;     // predicated STS (warp 7)
        c2i += 127 - (__float_as_int(sc) >> 23);   // uniform ALU, all lanes

        ef = ef_next; pA = pB; pB = pC;
    };

    // ---------------- recursion, unrolled by 2 ----------------
    int t = 1;
    for (; t + 1 < len; t += 2) {
        step(t,     0, 1, eAs[0], eAs[1]);
        step(t + 1, 1, 0, eAs[1], eAs[0]);
    }
    if (t < len) step(t, (t - 1) & 1, t & 1, eAs[(t - 1) & 1], eAs[t & 1]);

    // ---------------- terminal: log2(sum w) + exponent offset ----------------
    __syncthreads();
    red[tid] = (l < 16) ? eAs[(len - 1) & 1][jj] : 0.f;
    __syncthreads();
    #pragma unroll
    for (int s = NT / 2; s > 0; s >>= 1) {
        if (tid < s) red[tid] += red[tid + s];
        __syncthreads();
    }
    if (tid == 0) {
        float forward = ((float)c2i + c2f + lg2(red[0])) * LN2;
        g_partial[b] = forward - sh_gold;
        __threadfence();
        unsigned int f = atomicAdd(&g_count, 1);
        sh_last = (f == Bn - 1);
    }
    __syncthreads();

    if (sh_last) {
        __threadfence();
        red[tid] = (tid < Bn) ? g_partial[tid] : 0.f;
        __syncthreads();
        #pragma unroll
        for (int s = 32; s > 0; s >>= 1) {
            if (tid < s) red[tid] += red[tid + s];
            __syncthreads();
        }
        if (tid == 0) {
            out[0] = red[0] * (1.0f / Bn);
            g_count = 0;
        }
    }
}

extern "C" void kernel_launch(void* const* d_in, const int* in_sizes, int n_in,
                              void* d_out, int out_size)
{
    const float* feats = (const float*)d_in[0];
    const int*   tags  = (const int*)d_in[1];
    const int*   lens  = (const int*)d_in[2];
    const float* trans = (const float*)d_in[3];
    float* out = (float*)d_out;

    crf_fwd_kernel<<<Bn, NT>>>(feats, tags, lens, trans, out);
}

// round 9
// speedup vs baseline: 1.1520x; 1.1520x over previous
#include <cuda_runtime.h>
#include <math.h>

#define Bn 64
#define Tn 1024
#define Kn 128
#define NT 256
#define TAG_START 126
#define TAG_STOP  127
#define NEGV -10000.0f
#define LOG2E 1.4426950408889634f
#define LN2   0.6931471805599453f

__device__ float g_partial[Bn];
__device__ unsigned int g_count = 0;

#define FMA2(acc, x, y) \
    asm("fma.rn.f32x2 %0, %1, %2, %0;" : "+l"(acc) : "l"(x), "l"(y))

#define ADD2(dst, x, y) \
    asm("add.rn.f32x2 %0, %1, %2;" : "=l"(dst) : "l"(x), "l"(y))

#define PACK2(dst, lo, hi) \
    asm("mov.b64 %0, {%1, %2};" : "=l"(dst) : "f"(lo), "f"(hi))

#define UNPACK2(lo, hi, src) \
    asm("mov.b64 {%0, %1}, %2;" : "=f"(lo), "=f"(hi) : "l"(src))

__device__ __forceinline__ float ex2(float x) {
    float r; asm("ex2.approx.f32 %0, %1;" : "=f"(r) : "f"(x)); return r;
}
__device__ __forceinline__ float lg2(float x) {
    float r; asm("lg2.approx.f32 %0, %1;" : "=f"(r) : "f"(x)); return r;
}

__global__ __launch_bounds__(NT, 1) void crf_fwd_kernel(
    const float* __restrict__ feats,
    const int*   __restrict__ tags,
    const int*   __restrict__ lens,
    const float* __restrict__ trans,
    float*       __restrict__ out)
{
    const int b   = blockIdx.x;
    const int tid = threadIdx.x;
    const int w   = tid >> 5;          // warp 0..7
    const int l   = tid & 31;          // lane
    const int half = l >> 4;           // 0: inputs [0,64), 1: inputs [64,128)
    const int jj  = (w << 4) | (l & 15);   // output tag 0..127 (pair (l, l^16) shares jj)

    const float* fb = feats + (size_t)b * Tn * Kn;
    const int*   tb = tags + b * Tn;
    const int    len = lens[b];

    __shared__ __align__(16) float eAs[2][Kn];
    __shared__ float sv0[2];           // lagged power-of-2 scale
    __shared__ float red[NT];
    __shared__ float sh_gold;
    __shared__ float sh_ci;            // accumulated exponent (from lane 16)
    __shared__ int   sh_last;

    // ---------------- gold score (parallel over t, natural log) ----------------
    float gsum = 0.f;
    for (int t = tid; t < Tn; t += NT) {
        if (t < len)     gsum += fb[t * Kn + tb[t]];
        if (t < len - 1) gsum += trans[tb[t + 1] * Kn + tb[t]];
    }
    red[tid] = gsum;
    __syncthreads();
    #pragma unroll
    for (int s = NT / 2; s > 0; s >>= 1) {
        if (tid < s) red[tid] += red[tid + s];
        __syncthreads();
    }
    if (tid == 0) sh_gold = red[0];

    // ---------------- precompute exp(trans) half-row into 32 regs ----------------
    unsigned long long eT2[32];
    const float* trow = trans + jj * Kn + half * 64;
    #pragma unroll
    for (int i = 0; i < 32; i++) {
        float e0 = ex2(trow[2 * i]     * LOG2E);
        float e1 = ex2(trow[2 * i + 1] * LOG2E);
        PACK2(eT2[i], e0, e1);
    }

    // ---------------- init (t = 0), linear domain ----------------
    float f0s = fb[TAG_START];
    float c2f = f0s * LOG2E;
    if (l < 16) eAs[0][jj] = (jj == TAG_START) ? 1.f : 0.f;
    if (tid == 0) { sv0[0] = 1.f; sh_ci = 0.f; }
    int prev_e = 0;                    // exponent applied via sv0 (lane (0,16) tracks)
    int c2i = 0;

    // depth-3 feat prefetch (all lanes load; duplicates hit L1)
    float fA = (1 < len) ? fb[1 * Kn + jj] : 0.f;
    float pA = (2 < len) ? fb[2 * Kn + jj] : 0.f;
    float pB = (3 < len) ? fb[3 * Kn + jj] : 0.f;
    float ef = ex2(fA * LOG2E);

    // ---------------- sequential forward recursion (1 barrier/step) ----------------
    for (int t = 1; t < len; t++) {
        const int cur = (t - 1) & 1;
        const int nxt = t & 1;

        float pC = (t + 3 < len) ? fb[(t + 3) * Kn + jj] : 0.f;
        float ef_next = ex2(pA * LOG2E);        // hidden under this step's GEMV

        __syncthreads();                        // publishes eAs[cur], sv0[cur]
        float sc  = sv0[cur];
        float efs = ef * sc;                    // off the critical chain

        const ulonglong2* __restrict__ pV =
            (const ulonglong2*)(eAs[cur] + half * 64);
        unsigned long long acc0 = 0ull, acc1 = 0ull, acc2 = 0ull, acc3 = 0ull;
        #pragma unroll
        for (int i = 0; i < 8; i++) {
            ulonglong2 p = pV[i];               // LDS.128 broadcast
            FMA2(acc0, p.x, eT2[2 * i]);
            FMA2(acc1, p.y, eT2[2 * i + 1]);
        }
        #pragma unroll
        for (int i = 8; i < 16; i++) {
            ulonglong2 p = pV[i];               // LDS.128 broadcast
            FMA2(acc2, p.x, eT2[2 * i]);
            FMA2(acc3, p.y, eT2[2 * i + 1]);
        }
        unsigned long long s01, s23, sall;
        ADD2(s01, acc0, acc1);
        ADD2(s23, acc2, acc3);
        ADD2(sall, s01, s23);
        float lo, hi;
        UNPACK2(lo, hi, sall);
        float part = lo + hi;

        float other = __shfl_xor_sync(0xffffffffu, part, 16);
        float wv = (part + other) * efs;
        if (l < 16) eAs[nxt][jj] = wv;          // store half publishes
        if (w == 0 && l == 16) {                // redundant w[0] lane: renorm publish
            c2i += prev_e;
            int e = (__float_as_int(wv) >> 23) - 127;      // wv > 0, normal
            sv0[nxt] = __int_as_float((127 - e) << 23);    // 2^-e exactly
            prev_e = e;
        }

        ef = ef_next; fA = pA; pA = pB; pB = pC;
    }

    if (w == 0 && l == 16) sh_ci = (float)c2i;

    // ---------------- terminal: log2(sum w) + exponent offset ----------------
    __syncthreads();
    red[tid] = (l < 16) ? eAs[(len - 1) & 1][jj] : 0.f;
    __syncthreads();
    #pragma unroll
    for (int s = NT / 2; s > 0; s >>= 1) {
        if (tid < s) red[tid] += red[tid + s];
        __syncthreads();
    }
    if (tid == 0) {
        float forward = (sh_ci + c2f + lg2(red[0])) * LN2;
        g_partial[b] = forward - sh_gold;
        __threadfence();
        unsigned int f = atomicAdd(&g_count, 1);
        sh_last = (f == Bn - 1);
    }
    __syncthreads();

    // last block to finish reduces the mean
    if (sh_last) {
        __threadfence();
        red[tid] = (tid < Bn) ? g_partial[tid] : 0.f;
        __syncthreads();
        #pragma unroll
        for (int s = 32; s > 0; s >>= 1) {
            if (tid < s) red[tid] += red[tid + s];
            __syncthreads();
        }
        if (tid == 0) {
            out[0] = red[0] * (1.0f / Bn);
            g_count = 0;               // reset for graph replay
        }
    }
}

extern "C" void kernel_launch(void* const* d_in, const int* in_sizes, int n_in,
                              void* d_out, int out_size)
{
    const float* feats = (const float*)d_in[0];
    const int*   tags  = (const int*)d_in[1];
    const int*   lens  = (const int*)d_in[2];
    const float* trans = (const float*)d_in[3];
    float* out = (float*)d_out;

    crf_fwd_kernel<<<Bn, NT>>>(feats, tags, lens, trans, out);
}

// round 11
// speedup vs baseline: 1.3152x; 1.1416x over previous
#include <cuda_runtime.h>
#include <math.h>

#define Bn 64
#define Tn 1024
#define Kn 128
#define TAG_START 126
#define TAG_STOP  127
#define NEGV -10000.0f
#define LOG2E 1.4426950408889634f
#define LN2   0.6931471805599453f

__device__ float g_partial[Bn];
__device__ unsigned int g_count = 0;

#define FMA2(acc, x, y) \
    asm("fma.rn.f32x2 %0, %1, %2, %0;" : "+l"(acc) : "l"(x), "l"(y))

#define ADD2(dst, x, y) \
    asm("add.rn.f32x2 %0, %1, %2;" : "=l"(dst) : "l"(x), "l"(y))

#define PACK2(dst, lo, hi) \
    asm("mov.b64 %0, {%1, %2};" : "=l"(dst) : "f"(lo), "f"(hi))

#define UNPACK2(lo, hi, src) \
    asm("mov.b64 {%0, %1}, %2;" : "=f"(lo), "=f"(hi) : "l"(src))

__device__ __forceinline__ float ex2(float x) {
    float r; asm("ex2.approx.f32 %0, %1;" : "=f"(r) : "f"(x)); return r;
}
__device__ __forceinline__ float lg2(float x) {
    float r; asm("lg2.approx.f32 %0, %1;" : "=f"(r) : "f"(x)); return r;
}

__global__ __launch_bounds__(128, 1) void crf_fwd_kernel(
    const float* __restrict__ feats,
    const int*   __restrict__ tags,
    const int*   __restrict__ lens,
    const float* __restrict__ trans,
    float*       __restrict__ out)
{
    const int b = blockIdx.x;
    const int j = threadIdx.x;          // tag index, 0..127
    const float* fb = feats + (size_t)b * Tn * Kn;
    const int*   tb = tags + b * Tn;
    const int    len = lens[b];

    __shared__ __align__(16) float eAs[2][Kn];
    __shared__ float sv0[2];            // lagged power-of-2 scale
    __shared__ float red[Kn];
    __shared__ float sh_gold;
    __shared__ int   sh_last;

    // ---------------- gold score (parallel over t, natural log) ----------------
    float gsum = 0.f;
    for (int t = j; t < Tn; t += Kn) {
        if (t < len)     gsum += fb[t * Kn + tb[t]];
        if (t < len - 1) gsum += trans[tb[t + 1] * Kn + tb[t]];
    }
    red[j] = gsum;
    __syncthreads();
    #pragma unroll
    for (int s = 64; s > 0; s >>= 1) {
        if (j < s) red[j] += red[j + s];
        __syncthreads();
    }
    if (j == 0) sh_gold = red[0];

    // ---------------- precompute exp(trans) row j into registers ----------------
    unsigned long long eT2[64];
    #pragma unroll
    for (int i = 0; i < 64; i++) {
        float e0 = ex2(trans[j * Kn + 2 * i]     * LOG2E);
        float e1 = ex2(trans[j * Kn + 2 * i + 1] * LOG2E);
        PACK2(eT2[i], e0, e1);
    }

    // ---------------- init (t = 0), linear domain ----------------
    // w[j] = exp(alpha0[j]) * 2^(-c2f): w[START]=1, others 0.
    float f0s = fb[TAG_START];
    float c2f = f0s * LOG2E;            // fractional part of exponent offset
    int   c2i = 0;                      // integer part (exact, uniform on all lanes)
    eAs[0][j] = (j == TAG_START) ? 1.f : 0.f;
    if (j == 0) sv0[0] = 1.f;

    // depth-3 feat prefetch: fA = feat[t], pA = feat[t+1], pB = feat[t+2] in flight
    float fA = (1 < len) ? fb[1 * Kn + j] : 0.f;
    float pA = (2 < len) ? fb[2 * Kn + j] : 0.f;
    float pB = (3 < len) ? fb[3 * Kn + j] : 0.f;
    float ef = ex2(fA * LOG2E);         // exp(feat[1][j])

    // ---------------- sequential forward recursion (1 barrier/step) ----------------
    for (int t = 1; t < len; t++) {
        const int cur = (t - 1) & 1;
        const int nxt = t & 1;

        // issue LDG for feat[t+3] (~2 steps of latency cover)
        float pC = (t + 3 < len) ? fb[(t + 3) * Kn + j] : 0.f;
        // MUFU for next step's exp(feat), fully hidden under this step's GEMV
        float ef_next = ex2(pA * LOG2E);

        __syncthreads();                 // publishes eAs[cur], sv0[cur]
        float sc = sv0[cur];             // lagged power-of-2 scale
        float efs = ef * sc;             // off the critical chain

        const ulonglong2* __restrict__ pV = (const ulonglong2*)eAs[cur];
        unsigned long long acc0 = 0ull, acc1 = 0ull, acc2 = 0ull, acc3 = 0ull;
        #pragma unroll
        for (int i = 0; i < 32; i++) {
            ulonglong2 p = pV[i];                       // LDS.128 broadcast
            if ((i & 1) == 0) {
                FMA2(acc0, p.x, eT2[2 * i]);
                FMA2(acc1, p.y, eT2[2 * i + 1]);
            } else {
                FMA2(acc2, p.x, eT2[2 * i]);
                FMA2(acc3, p.y, eT2[2 * i + 1]);
            }
        }
        unsigned long long s01, s23, sall;
        ADD2(s01, acc0, acc1);
        ADD2(s23, acc2, acc3);
        ADD2(sall, s01, s23);
        float lo, hi;
        UNPACK2(lo, hi, sall);
        float dot = lo + hi;

        float w = dot * efs;             // single FMUL after the dot
        eAs[nxt][j] = w;
        if (j == 0) {                    // j==0 owns w[0]: publish next scale only
            int e = (__float_as_int(w) >> 23) - 127;     // w > 0, normal
            sv0[nxt] = __int_as_float((127 - e) << 23);  // 2^-e exactly
        }
        // recover applied exponent from sc: uniform ALU on all lanes, off-chain
        c2i += 127 - (__float_as_int(sc) >> 23);

        ef = ef_next; fA = pA; pA = pB; pB = pC;
    }

    // ---------------- terminal: log2(sum w) + exponent offset ----------------
    __syncthreads();
    float wfin = eAs[(len - 1) & 1][j];
    red[j] = wfin;
    __syncthreads();
    #pragma unroll
    for (int s = 64; s > 0; s >>= 1) {
        if (j < s) red[j] += red[j + s];
        __syncthreads();
    }
    if (j == 0) {
        float forward = ((float)c2i + c2f + lg2(red[0])) * LN2;
        g_partial[b] = forward - sh_gold;
        __threadfence();
        unsigned int f = atomicAdd(&g_count, 1);
        sh_last = (f == Bn - 1);
    }
    __syncthreads();

    // last block to finish reduces the mean
    if (sh_last) {
        __threadfence();
        red[j] = (j < Bn) ? g_partial[j] : 0.f;
        __syncthreads();
        #pragma unroll
        for (int s = 32; s > 0; s >>= 1) {
            if (j < s) red[j] += red[j + s];
            __syncthreads();
        }
        if (j == 0) {
            out[0] = red[0] * (1.0f / Bn);
            g_count = 0;                 // reset for graph replay
        }
    }
}

extern "C" void kernel_launch(void* const* d_in, const int* in_sizes, int n_in,
                              void* d_out, int out_size)
{
    const float* feats = (const float*)d_in[0];
    const int*   tags  = (const int*)d_in[1];
    const int*   lens  = (const int*)d_in[2];
    const float* trans = (const float*)d_in[3];
    float* out = (float*)d_out;

    crf_fwd_kernel<<<Bn, Kn>>>(feats, tags, lens, trans, out);
}